// round 1
// baseline (speedup 1.0000x reference)
#include <cuda_runtime.h>
#include <cuda_bf16.h>
#include <cstdint>

// Problem constants (fixed by the dataset)
#define MAXN 40000
#define MAXE 640000
#define INF 128
#define HID 128
#define OUTF 64

// ---------------- device scratch (no allocation allowed) ----------------
__device__ float g_P[MAXN * HID];      // x @ W1l
__device__ float g_Z[MAXN * HID];      // x @ W1r + b1
__device__ float g_h[MAXN * HID];      // relu(mean_agg(P) + Z)
__device__ float g_P2[MAXN * OUTF];    // h @ W2l
__device__ float g_Z2[MAXN * OUTF];    // h @ W2r + b2
__device__ int g_cnt[MAXN];
__device__ int g_rowptr[MAXN + 1];
__device__ int g_fill[MAXN];
__device__ int g_src[MAXE];
__device__ int g_dst[MAXE];
__device__ int g_col[MAXE];

// ---------------- edge preprocessing ----------------
__global__ void k_zero_cnt(int n) {
    int i = blockIdx.x * blockDim.x + threadIdx.x;
    if (i < n) g_cnt[i] = 0;
}

// Convert edge_index (int64 OR int32, detected on-device) to int32 src/dst,
// and histogram dst counts.
__global__ void k_convert_hist(const void* __restrict__ ei, int E) {
    int e = blockIdx.x * blockDim.x + threadIdx.x;
    if (e >= E) return;
    const long long* p64 = (const long long*)ei;
    bool is64 = true;
#pragma unroll
    for (int j = 0; j < 4; j++) {
        unsigned long long v = (unsigned long long)p64[j];
        if (v >> 32) is64 = false;
    }
    int s, d;
    if (is64) {
        s = (int)p64[e];
        d = (int)p64[(size_t)E + e];
    } else {
        const int* p32 = (const int*)ei;
        s = p32[e];
        d = p32[E + e];
    }
    g_src[e] = s;
    g_dst[e] = d;
    atomicAdd(&g_cnt[d], 1);
}

// Single-block exclusive prefix scan of g_cnt -> g_rowptr / g_fill.
__global__ void k_scan(int n) {
    __shared__ int wsum[32];
    __shared__ int carry;
    int tid = threadIdx.x;
    int lane = tid & 31, warp = tid >> 5;
    if (tid == 0) carry = 0;
    __syncthreads();
    for (int base = 0; base < n; base += 1024) {
        int i = base + tid;
        int v = (i < n) ? g_cnt[i] : 0;
        int x = v;
#pragma unroll
        for (int off = 1; off < 32; off <<= 1) {
            int y = __shfl_up_sync(0xffffffffu, x, off);
            if (lane >= off) x += y;
        }
        if (lane == 31) wsum[warp] = x;
        __syncthreads();
        if (warp == 0) {
            int wv = wsum[lane];
            int wx = wv;
#pragma unroll
            for (int off = 1; off < 32; off <<= 1) {
                int y = __shfl_up_sync(0xffffffffu, wx, off);
                if (lane >= off) wx += y;
            }
            wsum[lane] = wx - wv;  // exclusive warp offsets
        }
        __syncthreads();
        int incl = x + wsum[warp] + carry;
        if (i < n) {
            g_rowptr[i] = incl - v;
            g_fill[i] = incl - v;
        }
        __syncthreads();
        if (tid == 1023) carry = incl;
        __syncthreads();
    }
    if (tid == 0) g_rowptr[n] = carry;
}

__global__ void k_fill(int E) {
    int e = blockIdx.x * blockDim.x + threadIdx.x;
    if (e >= E) return;
    int d = g_dst[e];
    int pos = atomicAdd(&g_fill[d], 1);
    g_col[pos] = g_src[e];
}

// ---------------- GEMM: C[n x NC] = A[n x 128] * B[128 x NC] (+bias) ----------------
// BM=128, BK=16, 256 threads, per-thread tile 8 x TN.
template <int NC, int TN, bool HAS_BIAS>
__global__ __launch_bounds__(256, 2) void k_gemm_k128(
    const float* __restrict__ A, const float* __restrict__ B,
    const float* __restrict__ bias, float* __restrict__ C, int n) {
    constexpr int BM = 128, BK = 16;
    constexpr int TX = NC / TN;  // 16
    __shared__ float As[BK][BM + 4];  // stride 132: k-major, transposed A tile
    __shared__ float Bs[BK][NC];

    int i0 = blockIdx.x * BM;
    int tid = threadIdx.x;
    int tx = tid % TX;
    int ty = tid / TX;

    float acc[8][TN];
#pragma unroll
    for (int m = 0; m < 8; m++)
#pragma unroll
        for (int j = 0; j < TN; j++) acc[m][j] = 0.0f;

    for (int k0 = 0; k0 < 128; k0 += BK) {
        // load A tile (128 rows x 16 k) as float4, store transposed
#pragma unroll
        for (int l = 0; l < 2; l++) {
            int f = tid + l * 256;      // 0..511
            int row = f >> 2;           // 0..127
            int kq = f & 3;             // which float4 in the 16-k slab
            float4 v = make_float4(0.f, 0.f, 0.f, 0.f);
            int gi = i0 + row;
            if (gi < n) v = *(const float4*)(A + (size_t)gi * 128 + k0 + kq * 4);
            As[kq * 4 + 0][row] = v.x;
            As[kq * 4 + 1][row] = v.y;
            As[kq * 4 + 2][row] = v.z;
            As[kq * 4 + 3][row] = v.w;
        }
        // load B tile (16 x NC)
        constexpr int BF4 = BK * NC / 4;
#pragma unroll
        for (int f = tid; f < BF4; f += 256) {
            int kk = f / (NC / 4);
            int jq = f % (NC / 4);
            float4 v = *(const float4*)(B + (size_t)(k0 + kk) * NC + jq * 4);
            *(float4*)&Bs[kk][jq * 4] = v;
        }
        __syncthreads();
#pragma unroll
        for (int kk = 0; kk < BK; kk++) {
            float a[8], b[TN];
#pragma unroll
            for (int mq = 0; mq < 2; mq++) {
                float4 av = *(const float4*)&As[kk][ty * 8 + mq * 4];
                a[mq * 4 + 0] = av.x; a[mq * 4 + 1] = av.y;
                a[mq * 4 + 2] = av.z; a[mq * 4 + 3] = av.w;
            }
#pragma unroll
            for (int jq = 0; jq < TN / 4; jq++) {
                float4 bv = *(const float4*)&Bs[kk][tx * TN + jq * 4];
                b[jq * 4 + 0] = bv.x; b[jq * 4 + 1] = bv.y;
                b[jq * 4 + 2] = bv.z; b[jq * 4 + 3] = bv.w;
            }
#pragma unroll
            for (int m = 0; m < 8; m++)
#pragma unroll
                for (int j = 0; j < TN; j++) acc[m][j] += a[m] * b[j];
        }
        __syncthreads();
    }

    float bv[TN];
#pragma unroll
    for (int j = 0; j < TN; j++) bv[j] = HAS_BIAS ? bias[tx * TN + j] : 0.0f;

#pragma unroll
    for (int m = 0; m < 8; m++) {
        int gi = i0 + ty * 8 + m;
        if (gi < n) {
#pragma unroll
            for (int jq = 0; jq < TN / 4; jq++) {
                float4 v;
                v.x = acc[m][jq * 4 + 0] + bv[jq * 4 + 0];
                v.y = acc[m][jq * 4 + 1] + bv[jq * 4 + 1];
                v.z = acc[m][jq * 4 + 2] + bv[jq * 4 + 2];
                v.w = acc[m][jq * 4 + 3] + bv[jq * 4 + 3];
                *(float4*)(C + (size_t)gi * NC + tx * TN + jq * 4) = v;
            }
        }
    }
}

// ---------------- mean-aggregation epilogue kernels ----------------
// out[i] = act( mean_{e in row(i)} P[col[e]] + Z[i] ),  D=128 (float4/lane)
template <bool RELU>
__global__ void k_agg_add_128(const float4* __restrict__ P4,
                              const float4* __restrict__ Z4,
                              float4* __restrict__ out4, int n) {
    int w = (int)((blockIdx.x * (size_t)blockDim.x + threadIdx.x) >> 5);
    int lane = threadIdx.x & 31;
    if (w >= n) return;
    int s = g_rowptr[w], e = g_rowptr[w + 1];
    float4 acc = make_float4(0.f, 0.f, 0.f, 0.f);
    int j = s;
    for (; j + 4 <= e; j += 4) {
        int c0 = g_col[j], c1 = g_col[j + 1], c2 = g_col[j + 2], c3 = g_col[j + 3];
        float4 v0 = P4[(size_t)c0 * 32 + lane];
        float4 v1 = P4[(size_t)c1 * 32 + lane];
        float4 v2 = P4[(size_t)c2 * 32 + lane];
        float4 v3 = P4[(size_t)c3 * 32 + lane];
        acc.x += (v0.x + v1.x) + (v2.x + v3.x);
        acc.y += (v0.y + v1.y) + (v2.y + v3.y);
        acc.z += (v0.z + v1.z) + (v2.z + v3.z);
        acc.w += (v0.w + v1.w) + (v2.w + v3.w);
    }
    for (; j < e; j++) {
        int c = g_col[j];
        float4 v = P4[(size_t)c * 32 + lane];
        acc.x += v.x; acc.y += v.y; acc.z += v.z; acc.w += v.w;
    }
    int deg = e - s;
    float inv = 1.0f / (float)(deg > 0 ? deg : 1);
    float4 z = Z4[(size_t)w * 32 + lane];
    float4 r;
    r.x = acc.x * inv + z.x;
    r.y = acc.y * inv + z.y;
    r.z = acc.z * inv + z.z;
    r.w = acc.w * inv + z.w;
    if (RELU) {
        r.x = fmaxf(r.x, 0.f); r.y = fmaxf(r.y, 0.f);
        r.z = fmaxf(r.z, 0.f); r.w = fmaxf(r.w, 0.f);
    }
    out4[(size_t)w * 32 + lane] = r;
}

// D=64 variant (float2/lane), no relu (final layer)
__global__ void k_agg_add_64(const float2* __restrict__ P2,
                             const float2* __restrict__ Z2,
                             float2* __restrict__ out2, int n) {
    int w = (int)((blockIdx.x * (size_t)blockDim.x + threadIdx.x) >> 5);
    int lane = threadIdx.x & 31;
    if (w >= n) return;
    int s = g_rowptr[w], e = g_rowptr[w + 1];
    float2 acc = make_float2(0.f, 0.f);
    int j = s;
    for (; j + 4 <= e; j += 4) {
        int c0 = g_col[j], c1 = g_col[j + 1], c2 = g_col[j + 2], c3 = g_col[j + 3];
        float2 v0 = P2[(size_t)c0 * 32 + lane];
        float2 v1 = P2[(size_t)c1 * 32 + lane];
        float2 v2 = P2[(size_t)c2 * 32 + lane];
        float2 v3 = P2[(size_t)c3 * 32 + lane];
        acc.x += (v0.x + v1.x) + (v2.x + v3.x);
        acc.y += (v0.y + v1.y) + (v2.y + v3.y);
    }
    for (; j < e; j++) {
        int c = g_col[j];
        float2 v = P2[(size_t)c * 32 + lane];
        acc.x += v.x; acc.y += v.y;
    }
    int deg = e - s;
    float inv = 1.0f / (float)(deg > 0 ? deg : 1);
    float2 z = Z2[(size_t)w * 32 + lane];
    float2 r;
    r.x = acc.x * inv + z.x;
    r.y = acc.y * inv + z.y;
    out2[(size_t)w * 32 + lane] = r;
}

// ---------------- launch ----------------
extern "C" void kernel_launch(void* const* d_in, const int* in_sizes, int n_in,
                              void* d_out, int out_size) {
    const float* x = (const float*)d_in[0];
    const void* edge_index = d_in[1];
    const float* W1l = (const float*)d_in[2];
    const float* b1 = (const float*)d_in[3];
    const float* W1r = (const float*)d_in[4];
    const float* W2l = (const float*)d_in[5];
    const float* b2 = (const float*)d_in[6];
    const float* W2r = (const float*)d_in[7];
    float* out = (float*)d_out;

    int N = in_sizes[0] / INF;
    int E = in_sizes[1] / 2;
    if (N > MAXN) N = MAXN;
    if (E > MAXE) E = MAXE;

    float *p_P, *p_Z, *p_h, *p_P2, *p_Z2;
    cudaGetSymbolAddress((void**)&p_P, g_P);
    cudaGetSymbolAddress((void**)&p_Z, g_Z);
    cudaGetSymbolAddress((void**)&p_h, g_h);
    cudaGetSymbolAddress((void**)&p_P2, g_P2);
    cudaGetSymbolAddress((void**)&p_Z2, g_Z2);

    // CSR build
    k_zero_cnt<<<(N + 255) / 256, 256>>>(N);
    k_convert_hist<<<(E + 255) / 256, 256>>>(edge_index, E);
    k_scan<<<1, 1024>>>(N);
    k_fill<<<(E + 255) / 256, 256>>>(E);

    int gblocks = (N + 127) / 128;

    // Layer 1: P = x@W1l ; Z = x@W1r + b1 ; h = relu(mean_agg(P) + Z)
    k_gemm_k128<128, 8, false><<<gblocks, 256>>>(x, W1l, nullptr, p_P, N);
    k_gemm_k128<128, 8, true><<<gblocks, 256>>>(x, W1r, b1, p_Z, N);
    k_agg_add_128<true><<<(N * 32 + 255) / 256, 256>>>(
        (const float4*)p_P, (const float4*)p_Z, (float4*)p_h, N);

    // Layer 2: P2 = h@W2l ; Z2 = h@W2r + b2 ; out = mean_agg(P2) + Z2
    k_gemm_k128<64, 4, false><<<gblocks, 256>>>(p_h, W2l, nullptr, p_P2, N);
    k_gemm_k128<64, 4, true><<<gblocks, 256>>>(p_h, W2r, b2, p_Z2, N);
    k_agg_add_64<<<(N * 32 + 255) / 256, 256>>>(
        (const float2*)p_P2, (const float2*)p_Z2, (float2*)out, N);
}

// round 2
// speedup vs baseline: 1.0784x; 1.0784x over previous
#include <cuda_runtime.h>
#include <cuda_bf16.h>
#include <cstdint>

// Problem constants (fixed by the dataset)
#define MAXN 40000
#define MAXE 640000
#define INF 128
#define HID 128
#define OUTF 64

typedef unsigned long long ull;

// ---------------- packed f32x2 helpers (sm_103a) ----------------
__device__ __forceinline__ ull pack2(float lo, float hi) {
    ull r;
    asm("mov.b64 %0, {%1, %2};" : "=l"(r) : "f"(lo), "f"(hi));
    return r;
}
__device__ __forceinline__ ull ffma2(ull a, ull b, ull c) {
    ull d;
    asm("fma.rn.f32x2 %0, %1, %2, %3;" : "=l"(d) : "l"(a), "l"(b), "l"(c));
    return d;
}
__device__ __forceinline__ float2 unpack2(ull v) {
    float2 f;
    asm("mov.b64 {%0, %1}, %2;" : "=f"(f.x), "=f"(f.y) : "l"(v));
    return f;
}

// ---------------- device scratch (no allocation allowed) ----------------
__device__ float g_P[MAXN * HID];      // x @ W1l
__device__ float g_Z[MAXN * HID];      // x @ W1r + b1
__device__ float g_h[MAXN * HID];      // relu(mean_agg(P) + Z)
__device__ float g_P2[MAXN * OUTF];    // h @ W2l
__device__ float g_Z2[MAXN * OUTF];    // h @ W2r + b2
__device__ int g_cnt[MAXN];
__device__ int g_rowptr[MAXN + 1];
__device__ int g_fill[MAXN];
__device__ int g_src[MAXE];
__device__ int g_dst[MAXE];
__device__ int g_col[MAXE];

// ---------------- edge preprocessing ----------------
__global__ void k_zero_cnt(int n) {
    int i = blockIdx.x * blockDim.x + threadIdx.x;
    if (i < n) g_cnt[i] = 0;
}

// Convert edge_index (int64 OR int32, detected on-device) to int32 src/dst,
// and histogram dst counts.
__global__ void k_convert_hist(const void* __restrict__ ei, int E) {
    int e = blockIdx.x * blockDim.x + threadIdx.x;
    if (e >= E) return;
    const long long* p64 = (const long long*)ei;
    bool is64 = true;
#pragma unroll
    for (int j = 0; j < 4; j++) {
        unsigned long long v = (unsigned long long)p64[j];
        if (v >> 32) is64 = false;
    }
    int s, d;
    if (is64) {
        s = (int)p64[e];
        d = (int)p64[(size_t)E + e];
    } else {
        const int* p32 = (const int*)ei;
        s = p32[e];
        d = p32[E + e];
    }
    g_src[e] = s;
    g_dst[e] = d;
    atomicAdd(&g_cnt[d], 1);
}

// Single-block exclusive prefix scan of g_cnt -> g_rowptr / g_fill.
__global__ void k_scan(int n) {
    __shared__ int wsum[32];
    __shared__ int carry;
    int tid = threadIdx.x;
    int lane = tid & 31, warp = tid >> 5;
    if (tid == 0) carry = 0;
    __syncthreads();
    for (int base = 0; base < n; base += 1024) {
        int i = base + tid;
        int v = (i < n) ? g_cnt[i] : 0;
        int x = v;
#pragma unroll
        for (int off = 1; off < 32; off <<= 1) {
            int y = __shfl_up_sync(0xffffffffu, x, off);
            if (lane >= off) x += y;
        }
        if (lane == 31) wsum[warp] = x;
        __syncthreads();
        if (warp == 0) {
            int wv = wsum[lane];
            int wx = wv;
#pragma unroll
            for (int off = 1; off < 32; off <<= 1) {
                int y = __shfl_up_sync(0xffffffffu, wx, off);
                if (lane >= off) wx += y;
            }
            wsum[lane] = wx - wv;  // exclusive warp offsets
        }
        __syncthreads();
        int incl = x + wsum[warp] + carry;
        if (i < n) {
            g_rowptr[i] = incl - v;
            g_fill[i] = incl - v;
        }
        __syncthreads();
        if (tid == 1023) carry = incl;
        __syncthreads();
    }
    if (tid == 0) g_rowptr[n] = carry;
}

__global__ void k_fill(int E) {
    int e = blockIdx.x * blockDim.x + threadIdx.x;
    if (e >= E) return;
    int d = g_dst[e];
    int pos = atomicAdd(&g_fill[d], 1);
    g_col[pos] = g_src[e];
}

// ---------------- GEMM: C[n x NC] = A[n x 128] * B[128 x NC] (+bias) ----------------
// BM=128, BK=16, 256 threads, per-thread tile 8 x TN, packed f32x2 FMA inner loop.
template <int NC, int TN, bool HAS_BIAS>
__global__ __launch_bounds__(256) void k_gemm_k128(
    const float* __restrict__ A, const float* __restrict__ B,
    const float* __restrict__ bias, float* __restrict__ C, int n) {
    constexpr int BM = 128, BK = 16;
    constexpr int TX = NC / TN;  // 16
    constexpr int TP = TN / 2;   // packed pairs along j
    __shared__ float As[BK][BM + 4];  // k-major, transposed A tile
    __shared__ float Bs[BK][NC];

    int i0 = blockIdx.x * BM;
    int tid = threadIdx.x;
    int tx = tid % TX;
    int ty = tid / TX;

    ull acc2[8][TP];
#pragma unroll
    for (int m = 0; m < 8; m++)
#pragma unroll
        for (int p = 0; p < TP; p++) acc2[m][p] = 0ULL;  // two packed 0.0f

    for (int k0 = 0; k0 < 128; k0 += BK) {
        // load A tile (128 rows x 16 k) as float4, store transposed
#pragma unroll
        for (int l = 0; l < 2; l++) {
            int f = tid + l * 256;      // 0..511
            int row = f >> 2;           // 0..127
            int kq = f & 3;             // which float4 in the 16-k slab
            float4 v = make_float4(0.f, 0.f, 0.f, 0.f);
            int gi = i0 + row;
            if (gi < n) v = *(const float4*)(A + (size_t)gi * 128 + k0 + kq * 4);
            As[kq * 4 + 0][row] = v.x;
            As[kq * 4 + 1][row] = v.y;
            As[kq * 4 + 2][row] = v.z;
            As[kq * 4 + 3][row] = v.w;
        }
        // load B tile (16 x NC)
        constexpr int BF4 = BK * NC / 4;
#pragma unroll
        for (int f = tid; f < BF4; f += 256) {
            int kk = f / (NC / 4);
            int jq = f % (NC / 4);
            float4 v = *(const float4*)(B + (size_t)(k0 + kk) * NC + jq * 4);
            *(float4*)&Bs[kk][jq * 4] = v;
        }
        __syncthreads();
#pragma unroll
        for (int kk = 0; kk < BK; kk++) {
            // a: 8 rows, broadcast-packed
            float4 av0 = *(const float4*)&As[kk][ty * 8];
            float4 av1 = *(const float4*)&As[kk][ty * 8 + 4];
            ull a2[8];
            a2[0] = pack2(av0.x, av0.x);
            a2[1] = pack2(av0.y, av0.y);
            a2[2] = pack2(av0.z, av0.z);
            a2[3] = pack2(av0.w, av0.w);
            a2[4] = pack2(av1.x, av1.x);
            a2[5] = pack2(av1.y, av1.y);
            a2[6] = pack2(av1.z, av1.z);
            a2[7] = pack2(av1.w, av1.w);
            // b: TN cols as TP natural pairs
            ull b2[TP];
#pragma unroll
            for (int jq = 0; jq < TN / 4; jq++) {
                float4 bv = *(const float4*)&Bs[kk][tx * TN + jq * 4];
                b2[jq * 2 + 0] = pack2(bv.x, bv.y);
                b2[jq * 2 + 1] = pack2(bv.z, bv.w);
            }
#pragma unroll
            for (int m = 0; m < 8; m++)
#pragma unroll
                for (int p = 0; p < TP; p++)
                    acc2[m][p] = ffma2(a2[m], b2[p], acc2[m][p]);
        }
        __syncthreads();
    }

    float bv[TN];
#pragma unroll
    for (int j = 0; j < TN; j++) bv[j] = HAS_BIAS ? bias[tx * TN + j] : 0.0f;

#pragma unroll
    for (int m = 0; m < 8; m++) {
        int gi = i0 + ty * 8 + m;
        if (gi < n) {
#pragma unroll
            for (int jq = 0; jq < TN / 4; jq++) {
                float2 f0 = unpack2(acc2[m][jq * 2 + 0]);
                float2 f1 = unpack2(acc2[m][jq * 2 + 1]);
                float4 v;
                v.x = f0.x + bv[jq * 4 + 0];
                v.y = f0.y + bv[jq * 4 + 1];
                v.z = f1.x + bv[jq * 4 + 2];
                v.w = f1.y + bv[jq * 4 + 3];
                *(float4*)(C + (size_t)gi * NC + tx * TN + jq * 4) = v;
            }
        }
    }
}

// ---------------- mean-aggregation epilogue kernels ----------------
// out[i] = act( mean_{e in row(i)} P[col[e]] + Z[i] ),  D=128 (float4/lane)
template <bool RELU>
__global__ void k_agg_add_128(const float4* __restrict__ P4,
                              const float4* __restrict__ Z4,
                              float4* __restrict__ out4, int n) {
    int w = (int)((blockIdx.x * (size_t)blockDim.x + threadIdx.x) >> 5);
    int lane = threadIdx.x & 31;
    if (w >= n) return;
    int s = g_rowptr[w], e = g_rowptr[w + 1];
    float4 acc = make_float4(0.f, 0.f, 0.f, 0.f);
    int j = s;
    for (; j + 4 <= e; j += 4) {
        int c0 = g_col[j], c1 = g_col[j + 1], c2 = g_col[j + 2], c3 = g_col[j + 3];
        float4 v0 = P4[(size_t)c0 * 32 + lane];
        float4 v1 = P4[(size_t)c1 * 32 + lane];
        float4 v2 = P4[(size_t)c2 * 32 + lane];
        float4 v3 = P4[(size_t)c3 * 32 + lane];
        acc.x += (v0.x + v1.x) + (v2.x + v3.x);
        acc.y += (v0.y + v1.y) + (v2.y + v3.y);
        acc.z += (v0.z + v1.z) + (v2.z + v3.z);
        acc.w += (v0.w + v1.w) + (v2.w + v3.w);
    }
    for (; j < e; j++) {
        int c = g_col[j];
        float4 v = P4[(size_t)c * 32 + lane];
        acc.x += v.x; acc.y += v.y; acc.z += v.z; acc.w += v.w;
    }
    int deg = e - s;
    float inv = 1.0f / (float)(deg > 0 ? deg : 1);
    float4 z = Z4[(size_t)w * 32 + lane];
    float4 r;
    r.x = acc.x * inv + z.x;
    r.y = acc.y * inv + z.y;
    r.z = acc.z * inv + z.z;
    r.w = acc.w * inv + z.w;
    if (RELU) {
        r.x = fmaxf(r.x, 0.f); r.y = fmaxf(r.y, 0.f);
        r.z = fmaxf(r.z, 0.f); r.w = fmaxf(r.w, 0.f);
    }
    out4[(size_t)w * 32 + lane] = r;
}

// D=64 variant (float2/lane), no relu (final layer)
__global__ void k_agg_add_64(const float2* __restrict__ P2,
                             const float2* __restrict__ Z2,
                             float2* __restrict__ out2, int n) {
    int w = (int)((blockIdx.x * (size_t)blockDim.x + threadIdx.x) >> 5);
    int lane = threadIdx.x & 31;
    if (w >= n) return;
    int s = g_rowptr[w], e = g_rowptr[w + 1];
    float2 acc = make_float2(0.f, 0.f);
    int j = s;
    for (; j + 4 <= e; j += 4) {
        int c0 = g_col[j], c1 = g_col[j + 1], c2 = g_col[j + 2], c3 = g_col[j + 3];
        float2 v0 = P2[(size_t)c0 * 32 + lane];
        float2 v1 = P2[(size_t)c1 * 32 + lane];
        float2 v2 = P2[(size_t)c2 * 32 + lane];
        float2 v3 = P2[(size_t)c3 * 32 + lane];
        acc.x += (v0.x + v1.x) + (v2.x + v3.x);
        acc.y += (v0.y + v1.y) + (v2.y + v3.y);
    }
    for (; j < e; j++) {
        int c = g_col[j];
        float2 v = P2[(size_t)c * 32 + lane];
        acc.x += v.x; acc.y += v.y;
    }
    int deg = e - s;
    float inv = 1.0f / (float)(deg > 0 ? deg : 1);
    float2 z = Z2[(size_t)w * 32 + lane];
    float2 r;
    r.x = acc.x * inv + z.x;
    r.y = acc.y * inv + z.y;
    out2[(size_t)w * 32 + lane] = r;
}

// ---------------- launch ----------------
extern "C" void kernel_launch(void* const* d_in, const int* in_sizes, int n_in,
                              void* d_out, int out_size) {
    const float* x = (const float*)d_in[0];
    const void* edge_index = d_in[1];
    const float* W1l = (const float*)d_in[2];
    const float* b1 = (const float*)d_in[3];
    const float* W1r = (const float*)d_in[4];
    const float* W2l = (const float*)d_in[5];
    const float* b2 = (const float*)d_in[6];
    const float* W2r = (const float*)d_in[7];
    float* out = (float*)d_out;

    int N = in_sizes[0] / INF;
    int E = in_sizes[1] / 2;
    if (N > MAXN) N = MAXN;
    if (E > MAXE) E = MAXE;

    float *p_P, *p_Z, *p_h, *p_P2, *p_Z2;
    cudaGetSymbolAddress((void**)&p_P, g_P);
    cudaGetSymbolAddress((void**)&p_Z, g_Z);
    cudaGetSymbolAddress((void**)&p_h, g_h);
    cudaGetSymbolAddress((void**)&p_P2, g_P2);
    cudaGetSymbolAddress((void**)&p_Z2, g_Z2);

    // CSR build
    k_zero_cnt<<<(N + 255) / 256, 256>>>(N);
    k_convert_hist<<<(E + 255) / 256, 256>>>(edge_index, E);
    k_scan<<<1, 1024>>>(N);
    k_fill<<<(E + 255) / 256, 256>>>(E);

    int gblocks = (N + 127) / 128;

    // Layer 1: P = x@W1l ; Z = x@W1r + b1 ; h = relu(mean_agg(P) + Z)
    k_gemm_k128<128, 8, false><<<gblocks, 256>>>(x, W1l, nullptr, p_P, N);
    k_gemm_k128<128, 8, true><<<gblocks, 256>>>(x, W1r, b1, p_Z, N);
    k_agg_add_128<true><<<(N * 32 + 255) / 256, 256>>>(
        (const float4*)p_P, (const float4*)p_Z, (float4*)p_h, N);

    // Layer 2: P2 = h@W2l ; Z2 = h@W2r + b2 ; out = mean_agg(P2) + Z2
    k_gemm_k128<64, 4, false><<<gblocks, 256>>>(p_h, W2l, nullptr, p_P2, N);
    k_gemm_k128<64, 4, true><<<gblocks, 256>>>(p_h, W2r, b2, p_Z2, N);
    k_agg_add_64<<<(N * 32 + 255) / 256, 256>>>(
        (const float2*)p_P2, (const float2*)p_Z2, (float2*)out, N);
}

// round 4
// speedup vs baseline: 1.1116x; 1.0308x over previous
#include <cuda_runtime.h>
#include <cuda_bf16.h>
#include <cstdint>

#define MAXN 40000
#define NPADROWS (MAXN + 64)
#define MAXE 640000
#define INF 128
#define HID 128
#define OUTF 64

// ---------------- device scratch ----------------
__device__ float g_P[MAXN * HID];       // x @ W1l
__device__ float g_Z[MAXN * HID];       // x @ W1r + b1
__device__ float g_P2[MAXN * OUTF];     // h @ W2l
__device__ float g_Z2[MAXN * OUTF];     // h @ W2r + b2
__device__ int g_cnt[MAXN];
__device__ int g_rowptr[MAXN + 1];
__device__ int g_fill[MAXN];
__device__ int g_src[MAXE];
__device__ int g_dst[MAXE];
__device__ int g_col[MAXE];
__device__ int g_part[64];
// bf16 pair (u32 = 2 bf16, low = even k) k-major operands
__device__ uint32_t g_x_hi[NPADROWS * 64];
__device__ uint32_t g_x_lo[NPADROWS * 64];
__device__ uint32_t g_h_hi[NPADROWS * 64];
__device__ uint32_t g_h_lo[NPADROWS * 64];
// transposed split weights, n-major: Wt[n][k]
__device__ uint32_t g_Wt1_hi[256 * 64];
__device__ uint32_t g_Wt1_lo[256 * 64];
__device__ uint32_t g_Wt2_hi[128 * 64];
__device__ uint32_t g_Wt2_lo[128 * 64];

// ---------------- helpers ----------------
__device__ __forceinline__ uint32_t bfpack(__nv_bfloat16 a, __nv_bfloat16 b) {
    return (uint32_t)__bfloat16_as_ushort(a) | ((uint32_t)__bfloat16_as_ushort(b) << 16);
}
__device__ __forceinline__ void split2(float x, float y, uint32_t& hi, uint32_t& lo) {
    __nv_bfloat16 hx = __float2bfloat16_rn(x), hy = __float2bfloat16_rn(y);
    float rx = x - __bfloat162float(hx), ry = y - __bfloat162float(hy);
    hi = bfpack(hx, hy);
    lo = bfpack(__float2bfloat16_rn(rx), __float2bfloat16_rn(ry));
}
__device__ __forceinline__ void mma_bf16(float* d, const uint32_t* a,
                                         uint32_t b0, uint32_t b1) {
    asm volatile(
        "mma.sync.aligned.m16n8k16.row.col.f32.bf16.bf16.f32 "
        "{%0,%1,%2,%3}, {%4,%5,%6,%7}, {%8,%9}, {%0,%1,%2,%3};"
        : "+f"(d[0]), "+f"(d[1]), "+f"(d[2]), "+f"(d[3])
        : "r"(a[0]), "r"(a[1]), "r"(a[2]), "r"(a[3]), "r"(b0), "r"(b1));
}

// ---------------- edge preprocessing ----------------
__global__ void k_zero_cnt(int n) {
    int i = blockIdx.x * blockDim.x + threadIdx.x;
    if (i < n) g_cnt[i] = 0;
}

__global__ void k_convert_hist(const void* __restrict__ ei, int E) {
    int e = blockIdx.x * blockDim.x + threadIdx.x;
    if (e >= E) return;
    const long long* p64 = (const long long*)ei;
    bool is64 = true;
#pragma unroll
    for (int j = 0; j < 4; j++) {
        unsigned long long v = (unsigned long long)p64[j];
        if (v >> 32) is64 = false;
    }
    int s, d;
    if (is64) {
        s = (int)p64[e];
        d = (int)p64[(size_t)E + e];
    } else {
        const int* p32 = (const int*)ei;
        s = p32[e];
        d = p32[E + e];
    }
    g_src[e] = s;
    g_dst[e] = d;
    atomicAdd(&g_cnt[d], 1);
}

// 3-kernel parallel exclusive scan of g_cnt -> g_rowptr/g_fill
__global__ void k_scan1(int n) {
    __shared__ int ws[32];
    int i = blockIdx.x * 1024 + threadIdx.x;
    int lane = threadIdx.x & 31, w = threadIdx.x >> 5;
    int v = (i < n) ? g_cnt[i] : 0;
    int s = __reduce_add_sync(0xffffffffu, v);
    if (lane == 0) ws[w] = s;
    __syncthreads();
    if (w == 0) {
        int t = ws[lane];
        t = __reduce_add_sync(0xffffffffu, t);
        if (lane == 0) g_part[blockIdx.x] = t;
    }
}
__global__ void k_scan2(int nb, int n) {
    if (threadIdx.x == 0) {
        int run = 0;
        for (int b = 0; b < nb; b++) {
            int t = g_part[b];
            g_part[b] = run;
            run += t;
        }
        g_rowptr[n] = run;
    }
}
__global__ void k_scan3(int n) {
    __shared__ int ws[32];
    int i = blockIdx.x * 1024 + threadIdx.x;
    int lane = threadIdx.x & 31, w = threadIdx.x >> 5;
    int v = (i < n) ? g_cnt[i] : 0;
    int x = v;
#pragma unroll
    for (int off = 1; off < 32; off <<= 1) {
        int y = __shfl_up_sync(0xffffffffu, x, off);
        if (lane >= off) x += y;
    }
    if (lane == 31) ws[w] = x;
    __syncthreads();
    if (w == 0) {
        int wv = ws[lane];
        int wx = wv;
#pragma unroll
        for (int off = 1; off < 32; off <<= 1) {
            int y = __shfl_up_sync(0xffffffffu, wx, off);
            if (lane >= off) wx += y;
        }
        ws[lane] = wx - wv;
    }
    __syncthreads();
    int excl = x - v + ws[w] + g_part[blockIdx.x];
    if (i < n) {
        g_rowptr[i] = excl;
        g_fill[i] = excl;
    }
}

__global__ void k_fill(int E) {
    int e = blockIdx.x * blockDim.x + threadIdx.x;
    if (e >= E) return;
    int d = g_dst[e];
    int pos = atomicAdd(&g_fill[d], 1);
    g_col[pos] = g_src[e];
}

// ---------------- weight transpose + bf16 split ----------------
// Wt[n][k] = [Wl|Wr][k][n], split into bf16 hi/lo pairs (u32).
template <int NTOT, int NHALF>
__global__ void k_wt(const float* __restrict__ Wl, const float* __restrict__ Wr,
                     uint32_t* __restrict__ Whi, uint32_t* __restrict__ Wlo) {
    // one thread per (n, kpair)
    int idx = blockIdx.x * blockDim.x + threadIdx.x;
    if (idx >= NTOT * 64) return;
    int nn = idx >> 6;
    int kp = idx & 63;
    const float* W = (nn < NHALF) ? Wl : Wr;
    int nc = (nn < NHALF) ? nn : nn - NHALF;
    float v0 = W[(2 * kp) * NHALF + nc];
    float v1 = W[(2 * kp + 1) * NHALF + nc];
    uint32_t hi, lo;
    split2(v0, v1, hi, lo);
    Whi[idx] = hi;
    Wlo[idx] = lo;
}

// ---------------- input split: f32 [rows][128] -> bf16 hi/lo pairs ----------------
__global__ void k_split(const float* __restrict__ A, uint32_t* __restrict__ hi,
                        uint32_t* __restrict__ lo, int npairs) {
    int i = blockIdx.x * blockDim.x + threadIdx.x;
    if (i >= npairs) return;
    float2 v = ((const float2*)A)[i];
    split2(v.x, v.y, hi[i], lo[i]);
}

// ---------------- warp-MMA split-bf16 GEMM ----------------
// C[row, 0:128] = A[row, 0:128] @ Wt^T (3-pass bf16 split, f32 accum)
// cols < split -> outL (width=split) ; cols >= split -> outR (width=128-split) + bias
// CTA: 64 rows, 128 threads (4 warps 2Mx2N), warp tile 32x64.
__global__ __launch_bounds__(128) void k_mma(
    const uint32_t* __restrict__ Ahi, const uint32_t* __restrict__ Alo,
    const uint32_t* __restrict__ Bhi, const uint32_t* __restrict__ Blo,
    const float* __restrict__ bias,
    float* __restrict__ outL, float* __restrict__ outR,
    int split, int n) {
    int tid = threadIdx.x;
    int wid = tid >> 5, lane = tid & 31;
    int q = lane & 3, g = lane >> 2;
    int warpM = wid >> 1, warpN = wid & 1;
    int rbase = blockIdx.x * 64 + warpM * 32 + g;   // thread's row (group row)

    float acc[2][8][4];
#pragma unroll
    for (int mt = 0; mt < 2; mt++)
#pragma unroll
        for (int nt = 0; nt < 8; nt++)
#pragma unroll
            for (int c = 0; c < 4; c++) acc[mt][nt][c] = 0.0f;

    const uint32_t* aH = Ahi + (size_t)rbase * 64;
    const uint32_t* aL = Alo + (size_t)rbase * 64;
    int colg = warpN * 64 + g;

#pragma unroll 4
    for (int ks = 0; ks < 8; ks++) {
        int kp = ks * 8 + q;
        uint32_t Ah[2][4], Al[2][4];
#pragma unroll
        for (int mt = 0; mt < 2; mt++) {
            const uint32_t* ph = aH + mt * 1024 + kp;  // mt*16 rows * 64 pairs
            const uint32_t* pl = aL + mt * 1024 + kp;
            Ah[mt][0] = ph[0];    // (r,     k..k+1)
            Ah[mt][1] = ph[512];  // (r+8,   k..k+1)
            Ah[mt][2] = ph[4];    // (r,     k+8..k+9)
            Ah[mt][3] = ph[516];  // (r+8,   k+8..k+9)
            Al[mt][0] = pl[0];
            Al[mt][1] = pl[512];
            Al[mt][2] = pl[4];
            Al[mt][3] = pl[516];
        }
#pragma unroll
        for (int nt = 0; nt < 8; nt++) {
            const uint32_t* pbh = Bhi + (size_t)(colg + nt * 8) * 64 + kp;
            const uint32_t* pbl = Blo + (size_t)(colg + nt * 8) * 64 + kp;
            uint32_t bh0 = pbh[0], bh1 = pbh[4];
            uint32_t bl0 = pbl[0], bl1 = pbl[4];
#pragma unroll
            for (int mt = 0; mt < 2; mt++) {
                mma_bf16(acc[mt][nt], Ah[mt], bh0, bh1);  // hi*hi
                mma_bf16(acc[mt][nt], Ah[mt], bl0, bl1);  // hi*lo
                mma_bf16(acc[mt][nt], Al[mt], bh0, bh1);  // lo*hi
            }
        }
    }

    // epilogue
    int wR = 128 - split;
#pragma unroll
    for (int mt = 0; mt < 2; mt++) {
        int r0 = rbase + mt * 16;
        int r1 = r0 + 8;
#pragma unroll
        for (int nt = 0; nt < 8; nt++) {
            int col = warpN * 64 + nt * 8 + q * 2;
            const float* a = acc[mt][nt];
            if (col < split) {
                if (r0 < n) *(float2*)(outL + (size_t)r0 * split + col) = make_float2(a[0], a[1]);
                if (r1 < n) *(float2*)(outL + (size_t)r1 * split + col) = make_float2(a[2], a[3]);
            } else {
                int c = col - split;
                float b0 = __ldg(bias + c), b1 = __ldg(bias + c + 1);
                if (r0 < n) *(float2*)(outR + (size_t)r0 * wR + c) = make_float2(a[0] + b0, a[1] + b1);
                if (r1 < n) *(float2*)(outR + (size_t)r1 * wR + c) = make_float2(a[2] + b0, a[3] + b1);
            }
        }
    }
}

// ---------------- mean-aggregation epilogues ----------------
// h = relu(mean_agg(P) + Z), emitted directly as bf16 hi/lo pairs.
__global__ void k_agg_add_128(const float4* __restrict__ P4,
                              const float4* __restrict__ Z4,
                              uint32_t* __restrict__ Hhi,
                              uint32_t* __restrict__ Hlo, int n) {
    int w = (int)((blockIdx.x * (size_t)blockDim.x + threadIdx.x) >> 5);
    int lane = threadIdx.x & 31;
    if (w >= n) return;
    int s = g_rowptr[w], e = g_rowptr[w + 1];
    float4 acc = make_float4(0.f, 0.f, 0.f, 0.f);
    int j = s;
    for (; j + 4 <= e; j += 4) {
        int c0 = g_col[j], c1 = g_col[j + 1], c2 = g_col[j + 2], c3 = g_col[j + 3];
        float4 v0 = P4[(size_t)c0 * 32 + lane];
        float4 v1 = P4[(size_t)c1 * 32 + lane];
        float4 v2 = P4[(size_t)c2 * 32 + lane];
        float4 v3 = P4[(size_t)c3 * 32 + lane];
        acc.x += (v0.x + v1.x) + (v2.x + v3.x);
        acc.y += (v0.y + v1.y) + (v2.y + v3.y);
        acc.z += (v0.z + v1.z) + (v2.z + v3.z);
        acc.w += (v0.w + v1.w) + (v2.w + v3.w);
    }
    for (; j < e; j++) {
        int c = g_col[j];
        float4 v = P4[(size_t)c * 32 + lane];
        acc.x += v.x; acc.y += v.y; acc.z += v.z; acc.w += v.w;
    }
    int deg = e - s;
    float inv = 1.0f / (float)(deg > 0 ? deg : 1);
    float4 z = Z4[(size_t)w * 32 + lane];
    float4 r;
    r.x = fmaxf(acc.x * inv + z.x, 0.f);
    r.y = fmaxf(acc.y * inv + z.y, 0.f);
    r.z = fmaxf(acc.z * inv + z.z, 0.f);
    r.w = fmaxf(acc.w * inv + z.w, 0.f);
    uint32_t h0, l0, h1, l1;
    split2(r.x, r.y, h0, l0);
    split2(r.z, r.w, h1, l1);
    ((uint2*)(Hhi + (size_t)w * 64))[lane] = make_uint2(h0, h1);
    ((uint2*)(Hlo + (size_t)w * 64))[lane] = make_uint2(l0, l1);
}

__global__ void k_agg_add_64(const float2* __restrict__ P2,
                             const float2* __restrict__ Z2,
                             float2* __restrict__ out2, int n) {
    int w = (int)((blockIdx.x * (size_t)blockDim.x + threadIdx.x) >> 5);
    int lane = threadIdx.x & 31;
    if (w >= n) return;
    int s = g_rowptr[w], e = g_rowptr[w + 1];
    float2 acc = make_float2(0.f, 0.f);
    int j = s;
    for (; j + 4 <= e; j += 4) {
        int c0 = g_col[j], c1 = g_col[j + 1], c2 = g_col[j + 2], c3 = g_col[j + 3];
        float2 v0 = P2[(size_t)c0 * 32 + lane];
        float2 v1 = P2[(size_t)c1 * 32 + lane];
        float2 v2 = P2[(size_t)c2 * 32 + lane];
        float2 v3 = P2[(size_t)c3 * 32 + lane];
        acc.x += (v0.x + v1.x) + (v2.x + v3.x);
        acc.y += (v0.y + v1.y) + (v2.y + v3.y);
    }
    for (; j < e; j++) {
        int c = g_col[j];
        float2 v = P2[(size_t)c * 32 + lane];
        acc.x += v.x; acc.y += v.y;
    }
    int deg = e - s;
    float inv = 1.0f / (float)(deg > 0 ? deg : 1);
    float2 z = Z2[(size_t)w * 32 + lane];
    float2 r;
    r.x = acc.x * inv + z.x;
    r.y = acc.y * inv + z.y;
    out2[(size_t)w * 32 + lane] = r;
}

// ---------------- launch ----------------
extern "C" void kernel_launch(void* const* d_in, const int* in_sizes, int n_in,
                              void* d_out, int out_size) {
    const float* x = (const float*)d_in[0];
    const void* edge_index = d_in[1];
    const float* W1l = (const float*)d_in[2];
    const float* b1 = (const float*)d_in[3];
    const float* W1r = (const float*)d_in[4];
    const float* W2l = (const float*)d_in[5];
    const float* b2 = (const float*)d_in[6];
    const float* W2r = (const float*)d_in[7];
    float* out = (float*)d_out;

    int N = in_sizes[0] / INF;
    int E = in_sizes[1] / 2;
    if (N > MAXN) N = MAXN;
    if (E > MAXE) E = MAXE;

    float *p_P, *p_Z, *p_P2, *p_Z2;
    cudaGetSymbolAddress((void**)&p_P, g_P);
    cudaGetSymbolAddress((void**)&p_Z, g_Z);
    cudaGetSymbolAddress((void**)&p_P2, g_P2);
    cudaGetSymbolAddress((void**)&p_Z2, g_Z2);
    uint32_t *xh, *xl, *hh, *hl, *w1h, *w1l, *w2h, *w2l;
    cudaGetSymbolAddress((void**)&xh, g_x_hi);
    cudaGetSymbolAddress((void**)&xl, g_x_lo);
    cudaGetSymbolAddress((void**)&hh, g_h_hi);
    cudaGetSymbolAddress((void**)&hl, g_h_lo);
    cudaGetSymbolAddress((void**)&w1h, g_Wt1_hi);
    cudaGetSymbolAddress((void**)&w1l, g_Wt1_lo);
    cudaGetSymbolAddress((void**)&w2h, g_Wt2_hi);
    cudaGetSymbolAddress((void**)&w2l, g_Wt2_lo);

    // CSR build
    int nb = (N + 1023) / 1024;
    k_zero_cnt<<<(N + 255) / 256, 256>>>(N);
    k_convert_hist<<<(E + 255) / 256, 256>>>(edge_index, E);
    k_scan1<<<nb, 1024>>>(N);
    k_scan2<<<1, 32>>>(nb, N);
    k_scan3<<<nb, 1024>>>(N);
    k_fill<<<(E + 255) / 256, 256>>>(E);

    // operand prep
    k_wt<256, 128><<<(256 * 64 + 255) / 256, 256>>>(W1l, W1r, w1h, w1l);
    k_wt<128, 64><<<(128 * 64 + 255) / 256, 256>>>(W2l, W2r, w2h, w2l);
    int xpairs = N * 64;
    k_split<<<(xpairs + 255) / 256, 256>>>(x, xh, xl, xpairs);

    int mblocks = (N + 63) / 64;

    // Layer 1: P = x@W1l ; Z = x@W1r + b1 ; h = relu(mean_agg(P) + Z) (as bf16 split)
    k_mma<<<mblocks, 128>>>(xh, xl, w1h, w1l, b1, p_P, p_P, 128, N);
    k_mma<<<mblocks, 128>>>(xh, xl, w1h + 128 * 64, w1l + 128 * 64, b1, p_Z, p_Z, 0, N);
    k_agg_add_128<<<(N * 32 + 255) / 256, 256>>>(
        (const float4*)p_P, (const float4*)p_Z, hh, hl, N);

    // Layer 2: P2|Z2 = h @ [W2l|W2r] (+b2 on Z2) ; out = mean_agg(P2) + Z2
    k_mma<<<mblocks, 128>>>(hh, hl, w2h, w2l, b2, p_P2, p_Z2, 64, N);
    k_agg_add_64<<<(N * 32 + 255) / 256, 256>>>(
        (const float2*)p_P2, (const float2*)p_Z2, (float2*)out, N);
}

// round 5
// speedup vs baseline: 1.7328x; 1.5588x over previous
#include <cuda_runtime.h>
#include <cuda_bf16.h>
#include <cstdint>

#define MAXN 40000
#define NPADROWS (MAXN + 64)
#define MAXE 640000
#define INF 128

// ---------------- device scratch ----------------
__device__ float g_P[MAXN * 128];       // x @ W1l
__device__ float g_Z[MAXN * 128];       // x @ W1r + b1
__device__ float g_P2[MAXN * 64];       // h @ W2l
__device__ float g_Z2[MAXN * 64];       // h @ W2r + b2
__device__ int g_cnt[MAXN];
__device__ int g_rowptr[MAXN + 1];
__device__ int g_fill[MAXN];
__device__ int g_src[MAXE];
__device__ int g_dst[MAXE];
__device__ int g_col[MAXE];
__device__ int g_part[64];
// x in MMA A-fragment layout: uint4{a0,a1,a2,a3} per (tile16, ks, lane)
#define XTILES (MAXN / 16 + 4)
__device__ uint4 g_xf_hi[XTILES * 8 * 32];
__device__ uint4 g_xf_lo[XTILES * 8 * 32];
// h row-major bf16 pairs (u32 = 2 bf16), 64 pairs/row
__device__ uint32_t g_h_hi[NPADROWS * 64];
__device__ uint32_t g_h_lo[NPADROWS * 64];
// weights in MMA B-fragment layout: uint2{b0,b1} per (ntile8, ks, lane)
__device__ uint2 g_Wf1_hi[32 * 8 * 32];
__device__ uint2 g_Wf1_lo[32 * 8 * 32];
__device__ uint2 g_Wf2_hi[16 * 8 * 32];
__device__ uint2 g_Wf2_lo[16 * 8 * 32];

// ---------------- helpers ----------------
__device__ __forceinline__ uint32_t bfpack(__nv_bfloat16 a, __nv_bfloat16 b) {
    return (uint32_t)__bfloat16_as_ushort(a) | ((uint32_t)__bfloat16_as_ushort(b) << 16);
}
__device__ __forceinline__ void split2(float x, float y, uint32_t& hi, uint32_t& lo) {
    __nv_bfloat16 hx = __float2bfloat16_rn(x), hy = __float2bfloat16_rn(y);
    float rx = x - __bfloat162float(hx), ry = y - __bfloat162float(hy);
    hi = bfpack(hx, hy);
    lo = bfpack(__float2bfloat16_rn(rx), __float2bfloat16_rn(ry));
}
__device__ __forceinline__ void mma_bf16(float* d, const uint32_t* a,
                                         uint32_t b0, uint32_t b1) {
    asm volatile(
        "mma.sync.aligned.m16n8k16.row.col.f32.bf16.bf16.f32 "
        "{%0,%1,%2,%3}, {%4,%5,%6,%7}, {%8,%9}, {%0,%1,%2,%3};"
        : "+f"(d[0]), "+f"(d[1]), "+f"(d[2]), "+f"(d[3])
        : "r"(a[0]), "r"(a[1]), "r"(a[2]), "r"(a[3]), "r"(b0), "r"(b1));
}

// split one bf16-pair (2 consecutive k floats of column nc of W[k][·])
__device__ __forceinline__ void wpair(const float* W, int ldw, int nc, int p,
                                      uint32_t& hi, uint32_t& lo) {
    float v0 = W[(2 * p) * ldw + nc];
    float v1 = W[(2 * p + 1) * ldw + nc];
    split2(v0, v1, hi, lo);
}

// ---------------- prep launch 1: zero counters + weight fragment pack ----------------
__global__ void k_prep0(const float* __restrict__ W1l, const float* __restrict__ W1r,
                        const float* __restrict__ W2l, const float* __restrict__ W2r,
                        int n, int zb) {
    int b = blockIdx.x;
    int tid = threadIdx.x;
    if (b < zb) {
        int i = b * 256 + tid;
        if (i < n) g_cnt[i] = 0;
        return;
    }
    b -= zb;
    if (b < 32) {  // W1 frag pack: 32 n-tiles (N=256)
        int idx = b * 256 + tid;            // (t*8+s)*32+lane
        int lane = idx & 31;
        int s = (idx >> 5) & 7;
        int t = idx >> 8;
        int nn = t * 8 + (lane >> 2);
        int q = lane & 3;
        const float* W = (nn < 128) ? W1l : W1r;
        int nc = (nn < 128) ? nn : nn - 128;
        uint32_t h0, l0, h1, l1;
        wpair(W, 128, nc, s * 8 + q, h0, l0);
        wpair(W, 128, nc, s * 8 + q + 4, h1, l1);
        g_Wf1_hi[idx] = make_uint2(h0, h1);
        g_Wf1_lo[idx] = make_uint2(l0, l1);
        return;
    }
    b -= 32;
    {  // W2 frag pack: 16 n-tiles (N=128)
        int idx = b * 256 + tid;
        if (idx >= 16 * 8 * 32) return;
        int lane = idx & 31;
        int s = (idx >> 5) & 7;
        int t = idx >> 8;
        int nn = t * 8 + (lane >> 2);
        int q = lane & 3;
        const float* W = (nn < 64) ? W2l : W2r;
        int nc = (nn < 64) ? nn : nn - 64;
        uint32_t h0, l0, h1, l1;
        wpair(W, 64, nc, s * 8 + q, h0, l0);
        wpair(W, 64, nc, s * 8 + q + 4, h1, l1);
        g_Wf2_hi[idx] = make_uint2(h0, h1);
        g_Wf2_lo[idx] = make_uint2(l0, l1);
    }
}

// ---------------- prep launch 2: x fragment split + edge convert/hist ----------------
__global__ void k_prep1(const float* __restrict__ x, const void* __restrict__ ei,
                        int n, int E, int st) {
    int b = blockIdx.x;
    int tid = threadIdx.x;
    if (b < st) {  // x -> A-fragment split: one block per 16-row tile
        int tile = b;
        int s = tid >> 5;
        int lane = tid & 31;
        int g = lane >> 2, q = lane & 3;
        int r0 = tile * 16 + g;
        int r1 = r0 + 8;
        int p0 = s * 8 + q;
        int p2 = p0 + 4;
        float2 f00 = make_float2(0.f, 0.f), f10 = f00, f02 = f00, f12 = f00;
        if (r0 < n) {
            f00 = *(const float2*)(x + (size_t)r0 * 128 + 2 * p0);
            f02 = *(const float2*)(x + (size_t)r0 * 128 + 2 * p2);
        }
        if (r1 < n) {
            f10 = *(const float2*)(x + (size_t)r1 * 128 + 2 * p0);
            f12 = *(const float2*)(x + (size_t)r1 * 128 + 2 * p2);
        }
        uint32_t a0h, a0l, a1h, a1l, a2h, a2l, a3h, a3l;
        split2(f00.x, f00.y, a0h, a0l);
        split2(f10.x, f10.y, a1h, a1l);
        split2(f02.x, f02.y, a2h, a2l);
        split2(f12.x, f12.y, a3h, a3l);
        int idx = (tile * 8 + s) * 32 + lane;
        g_xf_hi[idx] = make_uint4(a0h, a1h, a2h, a3h);
        g_xf_lo[idx] = make_uint4(a0l, a1l, a2l, a3l);
        return;
    }
    // edge convert + histogram
    int e = (b - st) * 256 + tid;
    if (e >= E) return;
    const long long* p64 = (const long long*)ei;
    bool is64 = true;
#pragma unroll
    for (int j = 0; j < 4; j++) {
        unsigned long long v = (unsigned long long)p64[j];
        if (v >> 32) is64 = false;
    }
    int s, d;
    if (is64) {
        s = (int)p64[e];
        d = (int)p64[(size_t)E + e];
    } else {
        const int* p32 = (const int*)ei;
        s = p32[e];
        d = p32[E + e];
    }
    g_src[e] = s;
    g_dst[e] = d;
    atomicAdd(&g_cnt[d], 1);
}

// ---------------- scan ----------------
__global__ void k_scan1(int n) {
    __shared__ int ws[32];
    int i = blockIdx.x * 1024 + threadIdx.x;
    int lane = threadIdx.x & 31, w = threadIdx.x >> 5;
    int v = (i < n) ? g_cnt[i] : 0;
    int s = __reduce_add_sync(0xffffffffu, v);
    if (lane == 0) ws[w] = s;
    __syncthreads();
    if (w == 0) {
        int t = ws[lane];
        t = __reduce_add_sync(0xffffffffu, t);
        if (lane == 0) g_part[blockIdx.x] = t;
    }
}
__global__ void k_scan2(int nb, int n) {  // one warp
    int lane = threadIdx.x;
    int carry = 0;
    for (int base = 0; base < nb; base += 32) {
        int i = base + lane;
        int v = (i < nb) ? g_part[i] : 0;
        int x = v;
#pragma unroll
        for (int off = 1; off < 32; off <<= 1) {
            int y = __shfl_up_sync(0xffffffffu, x, off);
            if (lane >= off) x += y;
        }
        if (i < nb) g_part[i] = carry + x - v;
        carry += __shfl_sync(0xffffffffu, x, 31);
    }
    if (lane == 0) g_rowptr[n] = carry;
}
__global__ void k_scan3(int n) {
    __shared__ int ws[32];
    int i = blockIdx.x * 1024 + threadIdx.x;
    int lane = threadIdx.x & 31, w = threadIdx.x >> 5;
    int v = (i < n) ? g_cnt[i] : 0;
    int x = v;
#pragma unroll
    for (int off = 1; off < 32; off <<= 1) {
        int y = __shfl_up_sync(0xffffffffu, x, off);
        if (lane >= off) x += y;
    }
    if (lane == 31) ws[w] = x;
    __syncthreads();
    if (w == 0) {
        int wv = ws[lane];
        int wx = wv;
#pragma unroll
        for (int off = 1; off < 32; off <<= 1) {
            int y = __shfl_up_sync(0xffffffffu, wx, off);
            if (lane >= off) wx += y;
        }
        ws[lane] = wx - wv;
    }
    __syncthreads();
    int excl = x - v + ws[w] + g_part[blockIdx.x];
    if (i < n) {
        g_rowptr[i] = excl;
        g_fill[i] = excl;
    }
}

// ---------------- GEMM1 (N=256, A-frag) + fused CSR fill ----------------
// 256 threads: 8 warps (2M x 4N), warp tile 32x64, CTA tile 64x256.
__global__ __launch_bounds__(256) void k_mma1_fill(
    const float* __restrict__ bias, float* __restrict__ outL,
    float* __restrict__ outR, int n, int mmaBlocks, int E) {
    if (blockIdx.x >= mmaBlocks) {  // CSR fill blocks
        int e = (blockIdx.x - mmaBlocks) * 256 + threadIdx.x;
        if (e < E) {
            int d = g_dst[e];
            int pos = atomicAdd(&g_fill[d], 1);
            g_col[pos] = g_src[e];
        }
        return;
    }
    int tid = threadIdx.x;
    int wid = tid >> 5, lane = tid & 31;
    int q = lane & 3, g = lane >> 2;
    int warpM = wid >> 2, warpN = wid & 3;
    int rbase = blockIdx.x * 64 + warpM * 32 + g;

    float acc[2][8][4];
#pragma unroll
    for (int mt = 0; mt < 2; mt++)
#pragma unroll
        for (int nt = 0; nt < 8; nt++)
#pragma unroll
            for (int c = 0; c < 4; c++) acc[mt][nt][c] = 0.0f;

    int tA0 = blockIdx.x * 4 + warpM * 2;

#pragma unroll 2
    for (int s = 0; s < 8; s++) {
        uint4 ah[2], al[2];
#pragma unroll
        for (int mt = 0; mt < 2; mt++) {
            int idx = ((tA0 + mt) * 8 + s) * 32 + lane;
            ah[mt] = g_xf_hi[idx];
            al[mt] = g_xf_lo[idx];
        }
#pragma unroll
        for (int nt = 0; nt < 8; nt++) {
            int idx = ((warpN * 8 + nt) * 8 + s) * 32 + lane;
            uint2 bh = g_Wf1_hi[idx];
            uint2 bl = g_Wf1_lo[idx];
#pragma unroll
            for (int mt = 0; mt < 2; mt++) {
                mma_bf16(acc[mt][nt], (const uint32_t*)&ah[mt], bh.x, bh.y);
                mma_bf16(acc[mt][nt], (const uint32_t*)&ah[mt], bl.x, bl.y);
                mma_bf16(acc[mt][nt], (const uint32_t*)&al[mt], bh.x, bh.y);
            }
        }
    }

#pragma unroll
    for (int mt = 0; mt < 2; mt++) {
        int r0 = rbase + mt * 16;
        int r1 = r0 + 8;
#pragma unroll
        for (int nt = 0; nt < 8; nt++) {
            int col = warpN * 64 + nt * 8 + q * 2;
            const float* a = acc[mt][nt];
            if (col < 128) {
                if (r0 < n) *(float2*)(outL + (size_t)r0 * 128 + col) = make_float2(a[0], a[1]);
                if (r1 < n) *(float2*)(outL + (size_t)r1 * 128 + col) = make_float2(a[2], a[3]);
            } else {
                int c = col - 128;
                float b0 = __ldg(bias + c), b1 = __ldg(bias + c + 1);
                if (r0 < n) *(float2*)(outR + (size_t)r0 * 128 + c) = make_float2(a[0] + b0, a[1] + b1);
                if (r1 < n) *(float2*)(outR + (size_t)r1 * 128 + c) = make_float2(a[2] + b0, a[3] + b1);
            }
        }
    }
}

// ---------------- GEMM2 (N=128, A row-layout h) ----------------
// 128 threads: 4 warps (2M x 2N), warp tile 32x64, CTA tile 64x128.
__global__ __launch_bounds__(256) void k_mma2(
    const float* __restrict__ bias, float* __restrict__ outL,
    float* __restrict__ outR, int n) {
    int tid = threadIdx.x;
    int wid = tid >> 5, lane = tid & 31;
    int q = lane & 3, g = lane >> 2;
    int warpM = wid >> 1, warpN = wid & 1;
    int rbase = blockIdx.x * 64 + warpM * 32 + g;

    float acc[2][8][4];
#pragma unroll
    for (int mt = 0; mt < 2; mt++)
#pragma unroll
        for (int nt = 0; nt < 8; nt++)
#pragma unroll
            for (int c = 0; c < 4; c++) acc[mt][nt][c] = 0.0f;

    const uint32_t* aH = g_h_hi + (size_t)rbase * 64;
    const uint32_t* aL = g_h_lo + (size_t)rbase * 64;

#pragma unroll 2
    for (int s = 0; s < 8; s++) {
        int kp = s * 8 + q;
        uint32_t Ah[2][4], Al[2][4];
#pragma unroll
        for (int mt = 0; mt < 2; mt++) {
            const uint32_t* ph = aH + mt * 1024 + kp;
            const uint32_t* pl = aL + mt * 1024 + kp;
            Ah[mt][0] = ph[0];
            Ah[mt][1] = ph[512];
            Ah[mt][2] = ph[4];
            Ah[mt][3] = ph[516];
            Al[mt][0] = pl[0];
            Al[mt][1] = pl[512];
            Al[mt][2] = pl[4];
            Al[mt][3] = pl[516];
        }
#pragma unroll
        for (int nt = 0; nt < 8; nt++) {
            int idx = ((warpN * 8 + nt) * 8 + s) * 32 + lane;
            uint2 bh = g_Wf2_hi[idx];
            uint2 bl = g_Wf2_lo[idx];
#pragma unroll
            for (int mt = 0; mt < 2; mt++) {
                mma_bf16(acc[mt][nt], Ah[mt], bh.x, bh.y);
                mma_bf16(acc[mt][nt], Ah[mt], bl.x, bl.y);
                mma_bf16(acc[mt][nt], Al[mt], bh.x, bh.y);
            }
        }
    }

#pragma unroll
    for (int mt = 0; mt < 2; mt++) {
        int r0 = rbase + mt * 16;
        int r1 = r0 + 8;
#pragma unroll
        for (int nt = 0; nt < 8; nt++) {
            int col = warpN * 64 + nt * 8 + q * 2;
            const float* a = acc[mt][nt];
            if (col < 64) {
                if (r0 < n) *(float2*)(outL + (size_t)r0 * 64 + col) = make_float2(a[0], a[1]);
                if (r1 < n) *(float2*)(outL + (size_t)r1 * 64 + col) = make_float2(a[2], a[3]);
            } else {
                int c = col - 64;
                float b0 = __ldg(bias + c), b1 = __ldg(bias + c + 1);
                if (r0 < n) *(float2*)(outR + (size_t)r0 * 64 + c) = make_float2(a[0] + b0, a[1] + b1);
                if (r1 < n) *(float2*)(outR + (size_t)r1 * 64 + c) = make_float2(a[2] + b0, a[3] + b1);
            }
        }
    }
}

// ---------------- mean-aggregation epilogues ----------------
// h = relu(mean_agg(P) + Z) emitted as row-major bf16 hi/lo pairs.
__global__ void k_agg_add_128(const float4* __restrict__ P4,
                              const float4* __restrict__ Z4,
                              uint32_t* __restrict__ Hhi,
                              uint32_t* __restrict__ Hlo, int n) {
    int w = (int)((blockIdx.x * (size_t)blockDim.x + threadIdx.x) >> 5);
    int lane = threadIdx.x & 31;
    if (w >= n) return;
    int s = g_rowptr[w], e = g_rowptr[w + 1];
    float4 acc = make_float4(0.f, 0.f, 0.f, 0.f);
    int j = s;
    for (; j + 4 <= e; j += 4) {
        int c0 = g_col[j], c1 = g_col[j + 1], c2 = g_col[j + 2], c3 = g_col[j + 3];
        float4 v0 = P4[(size_t)c0 * 32 + lane];
        float4 v1 = P4[(size_t)c1 * 32 + lane];
        float4 v2 = P4[(size_t)c2 * 32 + lane];
        float4 v3 = P4[(size_t)c3 * 32 + lane];
        acc.x += (v0.x + v1.x) + (v2.x + v3.x);
        acc.y += (v0.y + v1.y) + (v2.y + v3.y);
        acc.z += (v0.z + v1.z) + (v2.z + v3.z);
        acc.w += (v0.w + v1.w) + (v2.w + v3.w);
    }
    for (; j < e; j++) {
        int c = g_col[j];
        float4 v = P4[(size_t)c * 32 + lane];
        acc.x += v.x; acc.y += v.y; acc.z += v.z; acc.w += v.w;
    }
    int deg = e - s;
    float inv = 1.0f / (float)(deg > 0 ? deg : 1);
    float4 z = Z4[(size_t)w * 32 + lane];
    float4 r;
    r.x = fmaxf(acc.x * inv + z.x, 0.f);
    r.y = fmaxf(acc.y * inv + z.y, 0.f);
    r.z = fmaxf(acc.z * inv + z.z, 0.f);
    r.w = fmaxf(acc.w * inv + z.w, 0.f);
    uint32_t h0, l0, h1, l1;
    split2(r.x, r.y, h0, l0);
    split2(r.z, r.w, h1, l1);
    ((uint2*)(Hhi + (size_t)w * 64))[lane] = make_uint2(h0, h1);
    ((uint2*)(Hlo + (size_t)w * 64))[lane] = make_uint2(l0, l1);
}

__global__ void k_agg_add_64(const float2* __restrict__ P2,
                             const float2* __restrict__ Z2,
                             float2* __restrict__ out2, int n) {
    int w = (int)((blockIdx.x * (size_t)blockDim.x + threadIdx.x) >> 5);
    int lane = threadIdx.x & 31;
    if (w >= n) return;
    int s = g_rowptr[w], e = g_rowptr[w + 1];
    float2 acc = make_float2(0.f, 0.f);
    int j = s;
    for (; j + 4 <= e; j += 4) {
        int c0 = g_col[j], c1 = g_col[j + 1], c2 = g_col[j + 2], c3 = g_col[j + 3];
        float2 v0 = P2[(size_t)c0 * 32 + lane];
        float2 v1 = P2[(size_t)c1 * 32 + lane];
        float2 v2 = P2[(size_t)c2 * 32 + lane];
        float2 v3 = P2[(size_t)c3 * 32 + lane];
        acc.x += (v0.x + v1.x) + (v2.x + v3.x);
        acc.y += (v0.y + v1.y) + (v2.y + v3.y);
    }
    for (; j < e; j++) {
        int c = g_col[j];
        float2 v = P2[(size_t)c * 32 + lane];
        acc.x += v.x; acc.y += v.y;
    }
    int deg = e - s;
    float inv = 1.0f / (float)(deg > 0 ? deg : 1);
    float2 z = Z2[(size_t)w * 32 + lane];
    float2 r;
    r.x = acc.x * inv + z.x;
    r.y = acc.y * inv + z.y;
    out2[(size_t)w * 32 + lane] = r;
}

// ---------------- launch ----------------
extern "C" void kernel_launch(void* const* d_in, const int* in_sizes, int n_in,
                              void* d_out, int out_size) {
    const float* x = (const float*)d_in[0];
    const void* edge_index = d_in[1];
    const float* W1l = (const float*)d_in[2];
    const float* b1 = (const float*)d_in[3];
    const float* W1r = (const float*)d_in[4];
    const float* W2l = (const float*)d_in[5];
    const float* b2 = (const float*)d_in[6];
    const float* W2r = (const float*)d_in[7];
    float* out = (float*)d_out;

    int N = in_sizes[0] / INF;
    int E = in_sizes[1] / 2;
    if (N > MAXN) N = MAXN;
    if (E > MAXE) E = MAXE;

    float *p_P, *p_Z, *p_P2, *p_Z2;
    cudaGetSymbolAddress((void**)&p_P, g_P);
    cudaGetSymbolAddress((void**)&p_Z, g_Z);
    cudaGetSymbolAddress((void**)&p_P2, g_P2);
    cudaGetSymbolAddress((void**)&p_Z2, g_Z2);
    uint32_t *hh, *hl;
    cudaGetSymbolAddress((void**)&hh, g_h_hi);
    cudaGetSymbolAddress((void**)&hl, g_h_lo);

    // launch 1: zero counters + weight frag pack
    int zb = (N + 255) / 256;
    k_prep0<<<zb + 32 + 16, 256>>>(W1l, W1r, W2l, W2r, N, zb);

    // launch 2: x frag split + edge convert/hist
    int st = (N + 15) / 16;
    int hb = (E + 255) / 256;
    k_prep1<<<st + hb, 256>>>(x, edge_index, N, E, st);

    // scan chain
    int nb = (N + 1023) / 1024;
    k_scan1<<<nb, 1024>>>(N);
    k_scan2<<<1, 32>>>(nb, N);
    k_scan3<<<nb, 1024>>>(N);

    // layer 1 GEMM (fused N=256) + co-scheduled CSR fill
    int mblocks = (N + 63) / 64;
    k_mma1_fill<<<mblocks + hb, 256>>>(b1, p_P, p_Z, N, mblocks, E);

    // h = relu(mean_agg(P) + Z), as bf16 split rows
    k_agg_add_128<<<(N * 32 + 255) / 256, 256>>>(
        (const float4*)p_P, (const float4*)p_Z, hh, hl, N);

    // layer 2 GEMM (N=128 split 64/64) then final aggregation
    k_mma2<<<mblocks, 128>>>(b2, p_P2, p_Z2, N);
    k_agg_add_64<<<(N * 32 + 255) / 256, 256>>>(
        (const float2*)p_P2, (const float2*)p_Z2, (float2*)out, N);
}